// round 2
// baseline (speedup 1.0000x reference)
#include <cuda_runtime.h>
#include <math.h>

#define NN      50000
#define NE      1600000
#define IN_DIM  512
#define HID_DIM 256
#define OUT_DIM 64
#define ALPHA   0.1f

// ---------------- static device scratch (no allocations allowed) ----------------
__device__ float g_hidden[(size_t)NN * HID_DIM];   // 51.2 MB
__device__ float g_feat0 [(size_t)NN * OUT_DIM];   // 12.8 MB
__device__ float g_featA [(size_t)NN * OUT_DIM];
__device__ float g_featB [(size_t)NN * OUT_DIM];
__device__ int   g_deg_out[NN];
__device__ int   g_deg_in [NN];
__device__ float g_norm_src[NN];
__device__ float g_norm_dst[NN];
__device__ int   g_ptr [NN + 1];
__device__ int   g_fill[NN];
__device__ int   g_bsum[256];
__device__ int   g_csr_src[NE];
__device__ int   g_csr_eid[NE];
__device__ float g_s[NN];
__device__ float g_d[NN];
__device__ float g_e[NE];

// ---------------- init ----------------
__global__ void init_zero_kernel() {
    int i = blockIdx.x * blockDim.x + threadIdx.x;
    if (i < NN) {
        g_deg_out[i] = 0;
        g_deg_in[i]  = 0;
        g_fill[i]    = 0;
    }
}

// ---------------- degrees ----------------
__global__ void degree_kernel(const int* __restrict__ src, const int* __restrict__ dst) {
    int e = blockIdx.x * blockDim.x + threadIdx.x;
    if (e < NE) {
        atomicAdd(&g_deg_out[src[e]], 1);
        atomicAdd(&g_deg_in [dst[e]], 1);
    }
}

__global__ void norm_kernel() {
    int i = blockIdx.x * blockDim.x + threadIdx.x;
    if (i < NN) {
        g_norm_src[i] = rsqrtf((float)max(g_deg_out[i], 1));
        g_norm_dst[i] = rsqrtf((float)max(g_deg_in [i], 1));
    }
}

// ---------------- exclusive scan of deg_in -> g_ptr (3 kernels) ----------------
__global__ void scan_block_kernel() {
    __shared__ int s[512];
    int tid = threadIdx.x;
    int i = blockIdx.x * 512 + tid;
    int v = (i < NN) ? g_deg_in[i] : 0;
    s[tid] = v;
    __syncthreads();
    #pragma unroll
    for (int off = 1; off < 512; off <<= 1) {
        int t = (tid >= off) ? s[tid - off] : 0;
        __syncthreads();
        s[tid] += t;
        __syncthreads();
    }
    if (i < NN) g_ptr[i] = s[tid] - v;            // block-local exclusive
    if (tid == 511) g_bsum[blockIdx.x] = s[511];  // block total
}

__global__ void scan_bsum_kernel(int nb) {
    __shared__ int s[128];
    int tid = threadIdx.x;
    int v = (tid < nb) ? g_bsum[tid] : 0;
    s[tid] = v;
    __syncthreads();
    #pragma unroll
    for (int off = 1; off < 128; off <<= 1) {
        int t = (tid >= off) ? s[tid - off] : 0;
        __syncthreads();
        s[tid] += t;
        __syncthreads();
    }
    if (tid < nb) g_bsum[tid] = s[tid] - v;       // exclusive in place
}

__global__ void scan_add_kernel() {
    int i = blockIdx.x * blockDim.x + threadIdx.x;
    if (i < NN)       g_ptr[i] += g_bsum[i >> 9];
    else if (i == NN) g_ptr[NN] = NE;
}

// ---------------- CSR fill (dst-sorted edge list) ----------------
__global__ void csr_fill_kernel(const int* __restrict__ src, const int* __restrict__ dst) {
    int e = blockIdx.x * blockDim.x + threadIdx.x;
    if (e < NE) {
        int d = dst[e];
        int pos = g_ptr[d] + atomicAdd(&g_fill[d], 1);
        g_csr_src[pos] = src[e];
        g_csr_eid[pos] = e;
    }
}

// ---------------- SGEMM: C = op(A@B + bias), optional second output ----------------
template <int BM, int BN, int BK, int TM, int TN, bool RELU>
__global__ void sgemm_kernel(const float* __restrict__ A, const float* __restrict__ B,
                             const float* __restrict__ bias,
                             float* __restrict__ C, float* __restrict__ C2,
                             int M, int N, int K) {
    constexpr int THREADS = (BM / TM) * (BN / TN);
    __shared__ float As[BK][BM];
    __shared__ float Bs[BK][BN];

    const int tid  = threadIdx.x;
    const int tcol = tid % (BN / TN);
    const int trow = tid / (BN / TN);
    const int aBase = blockIdx.y * BM;
    const int bBase = blockIdx.x * BN;

    float acc[TM][TN];
    #pragma unroll
    for (int i = 0; i < TM; i++)
        #pragma unroll
        for (int j = 0; j < TN; j++) acc[i][j] = 0.0f;

    for (int k0 = 0; k0 < K; k0 += BK) {
        // A tile (transposed into smem)
        #pragma unroll
        for (int i = tid * 4; i < BM * BK; i += THREADS * 4) {
            int m = i / BK, k = i % BK;
            int gm = aBase + m;
            float4 v = make_float4(0.f, 0.f, 0.f, 0.f);
            if (gm < M) v = *reinterpret_cast<const float4*>(&A[(size_t)gm * K + k0 + k]);
            As[k + 0][m] = v.x; As[k + 1][m] = v.y; As[k + 2][m] = v.z; As[k + 3][m] = v.w;
        }
        // B tile
        #pragma unroll
        for (int i = tid * 4; i < BK * BN; i += THREADS * 4) {
            int k = i / BN, n = i % BN;
            *reinterpret_cast<float4*>(&Bs[k][n]) =
                *reinterpret_cast<const float4*>(&B[(size_t)(k0 + k) * N + bBase + n]);
        }
        __syncthreads();

        #pragma unroll
        for (int k = 0; k < BK; ++k) {
            float areg[TM], breg[TN];
            #pragma unroll
            for (int i = 0; i < TM; i++) areg[i] = As[k][trow * TM + i];
            #pragma unroll
            for (int j = 0; j < TN; j++) breg[j] = Bs[k][tcol * TN + j];
            #pragma unroll
            for (int i = 0; i < TM; i++)
                #pragma unroll
                for (int j = 0; j < TN; j++) acc[i][j] += areg[i] * breg[j];
        }
        __syncthreads();
    }

    #pragma unroll
    for (int i = 0; i < TM; i++) {
        int gm = aBase + trow * TM + i;
        if (gm >= M) continue;
        #pragma unroll
        for (int j = 0; j < TN; j += 4) {
            int gn = bBase + tcol * TN + j;
            float4 r;
            r.x = acc[i][j + 0] + bias[gn + 0];
            r.y = acc[i][j + 1] + bias[gn + 1];
            r.z = acc[i][j + 2] + bias[gn + 2];
            r.w = acc[i][j + 3] + bias[gn + 3];
            if (RELU) {
                r.x = fmaxf(r.x, 0.f); r.y = fmaxf(r.y, 0.f);
                r.z = fmaxf(r.z, 0.f); r.w = fmaxf(r.w, 0.f);
            }
            *reinterpret_cast<float4*>(&C[(size_t)gm * N + gn]) = r;
            if (C2) *reinterpret_cast<float4*>(&C2[(size_t)gm * N + gn]) = r;
        }
    }
}

// ---------------- propagation hop: warp per dst node, CSR gather ----------------
__global__ void prop_kernel(int dir) {
    const float* __restrict__ fin  = dir ? g_featB : g_featA;
    float*       __restrict__ fout = dir ? g_featA : g_featB;

    int wid  = (blockIdx.x * blockDim.x + threadIdx.x) >> 5;
    int lane = threadIdx.x & 31;
    if (wid >= NN) return;

    int beg = g_ptr[wid], end = g_ptr[wid + 1];
    float acc0 = 0.f, acc1 = 0.f;

    int j = beg;
    for (; j + 4 <= end; j += 4) {
        int s0 = g_csr_src[j + 0], s1 = g_csr_src[j + 1];
        int s2 = g_csr_src[j + 2], s3 = g_csr_src[j + 3];
        float w0 = g_norm_src[s0], w1 = g_norm_src[s1];
        float w2 = g_norm_src[s2], w3 = g_norm_src[s3];
        const float* p0 = &fin[(size_t)s0 * OUT_DIM];
        const float* p1 = &fin[(size_t)s1 * OUT_DIM];
        const float* p2 = &fin[(size_t)s2 * OUT_DIM];
        const float* p3 = &fin[(size_t)s3 * OUT_DIM];
        acc0 += w0 * p0[lane]      + w1 * p1[lane]      + w2 * p2[lane]      + w3 * p3[lane];
        acc1 += w0 * p0[lane + 32] + w1 * p1[lane + 32] + w2 * p2[lane + 32] + w3 * p3[lane + 32];
    }
    for (; j < end; ++j) {
        int s = g_csr_src[j];
        float w = g_norm_src[s];
        const float* p = &fin[(size_t)s * OUT_DIM];
        acc0 += w * p[lane];
        acc1 += w * p[lane + 32];
    }

    float nd = g_norm_dst[wid];
    size_t o = (size_t)wid * OUT_DIM;
    fout[o + lane]      = (1.0f - ALPHA) * nd * acc0 + ALPHA * g_feat0[o + lane];
    fout[o + 32 + lane] = (1.0f - ALPHA) * nd * acc1 + ALPHA * g_feat0[o + 32 + lane];
}

// ---------------- per-node attention dot products ----------------
__global__ void sd_kernel(const float* __restrict__ w_src, const float* __restrict__ w_dst) {
    int wid  = (blockIdx.x * blockDim.x + threadIdx.x) >> 5;
    int lane = threadIdx.x & 31;
    if (wid >= NN) return;
    size_t o = (size_t)wid * OUT_DIM;
    float f0 = g_featA[o + lane], f1 = g_featA[o + 32 + lane];
    float s = f0 * w_src[lane] + f1 * w_src[lane + 32];
    float d = f0 * w_dst[lane] + f1 * w_dst[lane + 32];
    #pragma unroll
    for (int off = 16; off; off >>= 1) {
        s += __shfl_xor_sync(0xFFFFFFFFu, s, off);
        d += __shfl_xor_sync(0xFFFFFFFFu, d, off);
    }
    if (lane == 0) { g_s[wid] = s; g_d[wid] = d; }
}

// ---------------- edge-softmax per dst node ----------------
__global__ void attn_kernel(float* __restrict__ attn_out) {
    int wid  = (blockIdx.x * blockDim.x + threadIdx.x) >> 5;
    int lane = threadIdx.x & 31;
    if (wid >= NN) return;
    int beg = g_ptr[wid], end = g_ptr[wid + 1];
    if (beg == end) return;
    float dn = g_d[wid];

    float m = -2.0f;  // tanh >= -1
    for (int j = beg + lane; j < end; j += 32) {
        float e = tanhf(g_s[g_csr_src[j]] + dn);
        g_e[j] = e;
        m = fmaxf(m, e);
    }
    #pragma unroll
    for (int off = 16; off; off >>= 1)
        m = fmaxf(m, __shfl_xor_sync(0xFFFFFFFFu, m, off));

    float sum = 0.f;
    for (int j = beg + lane; j < end; j += 32)
        sum += __expf(g_e[j] - m);
    #pragma unroll
    for (int off = 16; off; off >>= 1)
        sum += __shfl_xor_sync(0xFFFFFFFFu, sum, off);

    float inv = 1.0f / sum;
    for (int j = beg + lane; j < end; j += 32)
        attn_out[g_csr_eid[j]] = __expf(g_e[j] - m) * inv;
}

// ---------------- log_softmax over 64 features ----------------
__global__ void logsoftmax_kernel(float* __restrict__ out) {
    int wid  = (blockIdx.x * blockDim.x + threadIdx.x) >> 5;
    int lane = threadIdx.x & 31;
    if (wid >= NN) return;
    size_t o = (size_t)wid * OUT_DIM;
    float f0 = g_featA[o + lane], f1 = g_featA[o + 32 + lane];
    float m = fmaxf(f0, f1);
    #pragma unroll
    for (int off = 16; off; off >>= 1)
        m = fmaxf(m, __shfl_xor_sync(0xFFFFFFFFu, m, off));
    float sum = __expf(f0 - m) + __expf(f1 - m);
    #pragma unroll
    for (int off = 16; off; off >>= 1)
        sum += __shfl_xor_sync(0xFFFFFFFFu, sum, off);
    float ls = m + logf(sum);
    out[o + lane]      = f0 - ls;
    out[o + 32 + lane] = f1 - ls;
}

// ---------------- launch ----------------
extern "C" void kernel_launch(void* const* d_in, const int* in_sizes, int n_in,
                              void* d_out, int out_size) {
    const float* h     = (const float*)d_in[0];
    const int*   src   = (const int*)  d_in[1];
    const int*   dst   = (const int*)  d_in[2];
    const float* W1    = (const float*)d_in[3];
    const float* b1    = (const float*)d_in[4];
    const float* W2    = (const float*)d_in[5];
    const float* b2    = (const float*)d_in[6];
    const float* w_src = (const float*)d_in[7];
    const float* w_dst = (const float*)d_in[8];
    float* out = (float*)d_out;

    float *p_hidden, *p_feat0, *p_featA;
    cudaGetSymbolAddress((void**)&p_hidden, g_hidden);
    cudaGetSymbolAddress((void**)&p_feat0,  g_feat0);
    cudaGetSymbolAddress((void**)&p_featA,  g_featA);

    const int nodeBlocks = (NN + 255) / 256;
    const int edgeBlocks = (NE + 255) / 256;
    const int warpNodeBlocks = (NN + 7) / 8;  // 256 threads = 8 warps, warp per node
    const int nbScan = (NN + 511) / 512;      // 98

    init_zero_kernel<<<nodeBlocks, 256>>>();
    degree_kernel<<<edgeBlocks, 256>>>(src, dst);
    norm_kernel<<<nodeBlocks, 256>>>();
    scan_block_kernel<<<nbScan, 512>>>();
    scan_bsum_kernel<<<1, 128>>>(nbScan);
    scan_add_kernel<<<(NN + 1 + 255) / 256, 256>>>();
    csr_fill_kernel<<<edgeBlocks, 256>>>(src, dst);

    // GEMM1: hidden = relu(h @ W1 + b1)   [50000x512] @ [512x256]
    {
        dim3 grid(HID_DIM / 128, (NN + 127) / 128);
        sgemm_kernel<128, 128, 8, 8, 8, true><<<grid, 256>>>(
            h, W1, b1, p_hidden, nullptr, NN, HID_DIM, IN_DIM);
    }
    // GEMM2: feat0 = hidden @ W2 + b2     [50000x256] @ [256x64]  (also writes featA)
    {
        dim3 grid(OUT_DIM / 64, (NN + 127) / 128);
        sgemm_kernel<128, 64, 16, 8, 4, false><<<grid, 256>>>(
            p_hidden, W2, b2, p_feat0, p_featA, NN, OUT_DIM, HID_DIM);
    }

    // 4 propagation hops (ping-pong, ends in g_featA)
    prop_kernel<<<warpNodeBlocks, 256>>>(0);
    prop_kernel<<<warpNodeBlocks, 256>>>(1);
    prop_kernel<<<warpNodeBlocks, 256>>>(0);
    prop_kernel<<<warpNodeBlocks, 256>>>(1);

    sd_kernel<<<warpNodeBlocks, 256>>>(w_src, w_dst);
    attn_kernel<<<warpNodeBlocks, 256>>>(out + (size_t)NN * OUT_DIM);
    logsoftmax_kernel<<<warpNodeBlocks, 256>>>(out);
}